// round 10
// baseline (speedup 1.0000x reference)
#include <cuda_runtime.h>
#include <cuda_bf16.h>
#include <cstdint>

// DistortionLoss via quarter-ray threads.
//   loss = inv * [ sum_{i<j} w_i w_j (s_j - s_i) + (1/3) sum_k w_k^2 dz_k ],
//   s_k = z_k + z_{k+1}, all in raw z-space (near cancels, inv applied once).
//
// R10 structure: 4 threads per ray, 32 elements each, streamed serially in
// registers (no shuffles, no scan ladders). Quarter totals (TW, TWS) couple
// across quarters algebraically: cross(q<q') = TW_q*TWS_q' - TWS_q*TW_q',
// combined by warp 0 via a small smem table. Inputs are block-staged through
// smem with cp.async for coalescing (w padded to 132-float rows -> LDS.128
// conflict-free; z flat -> scalar LDS, bank = ray + c, conflict-free).
// Per-warp issue: ~420 slots covering 8 rays (~52/ray vs ~290 in the warp-
// per-ray design).

#define RAYS_PER_CTA 32
#define THREADS 128

__device__ __forceinline__ void cp_async16(void* smem_dst, const void* gmem_src) {
    uint32_t s = (uint32_t)__cvta_generic_to_shared(smem_dst);
    asm volatile("cp.async.cg.shared.global [%0], [%1], 16;\n" :: "r"(s), "l"(gmem_src));
}

__global__ void __launch_bounds__(THREADS) distortion_loss_kernel(
    const float*  __restrict__ w,     // [R,128]
    const float*  __restrict__ z,     // [R,129]
    const float*  __restrict__ nearp, // [R]
    const float*  __restrict__ farp,  // [R]
    float* __restrict__ out)          // [R]
{
    __shared__ float wsm[RAYS_PER_CTA * 132];   // padded w rows (conflict-free LDS.128)
    __shared__ float zs [RAYS_PER_CTA * 129];   // flat z block (1032 aligned quads)
    __shared__ float tw_s [4][RAYS_PER_CTA];
    __shared__ float tws_s[4][RAYS_PER_CTA];
    __shared__ float ai_s [4][RAYS_PER_CTA];

    const int tid = threadIdx.x;
    const int ray = tid & 31;        // ray within CTA; warp-consecutive
    const int q   = tid >> 5;        // quarter 0..3 == warp id
    const int R0  = blockIdx.x * RAYS_PER_CTA;

    // warp 0 prefetches near/far early (used only in finalize)
    float nr = 0.f, fr = 1.f;
    if (q == 0) { nr = __ldg(nearp + R0 + ray); fr = __ldg(farp + R0 + ray); }

    // ---- stage block inputs: w = 1024 quads (padded rows), z = 1032 quads (flat) ----
    {
        const float* wg = w + (size_t)R0 * 128;
        const float* zg = z + (size_t)R0 * 129;   // block region: 32*129 floats, quad-aligned
        #pragma unroll
        for (int j = 0; j < 17; j++) {
            const int idx = tid + THREADS * j;    // 0..2175, need < 2056
            if (idx < 1024) {
                cp_async16(&wsm[(idx >> 5) * 132 + (idx & 31) * 4], wg + 4 * idx);
            } else if (idx < 2056) {
                const int g = idx - 1024;
                cp_async16(&zs[4 * g], zg + 4 * g);
            }
        }
        asm volatile("cp.async.commit_group;\n" ::: "memory");
        asm volatile("cp.async.wait_group 0;\n" ::: "memory");
    }
    __syncthreads();

    // ---- per-thread streaming pass over 32 elements ----
    const float* wp = &wsm[ray * 132 + 32 * q];
    const float* zp = &zs [ray * 129 + 32 * q];

    float wreg[32];
    #pragma unroll
    for (int k = 0; k < 8; k++) {
        const float4 v = reinterpret_cast<const float4*>(wp)[k];
        wreg[4 * k + 0] = v.x; wreg[4 * k + 1] = v.y;
        wreg[4 * k + 2] = v.z; wreg[4 * k + 3] = v.w;
    }

    float W = 0.f, WS = 0.f, acc = 0.f, qq = 0.f;
    float zprev = zp[0];
    #pragma unroll
    for (int k = 0; k < 32; k++) {
        const float zn = zp[k + 1];
        const float wk = wreg[k];
        const float s  = zprev + zn;
        const float ws = wk * s;
        const float t  = fmaf(s, W, -WS);      // s_k*W_< - WS_<
        acc = fmaf(wk, t, acc);
        qq  = fmaf(wk * wk, zn - zprev, qq);
        W  += wk;
        WS += ws;
        zprev = zn;
    }
    const float intra = fmaf(qq, (1.0f / 3.0f), acc);

    tw_s [q][ray] = W;
    tws_s[q][ray] = WS;
    ai_s [q][ray] = intra;
    __syncthreads();

    // ---- finalize: warp 0, one thread per ray ----
    if (q == 0) {
        float A = tw_s[0][ray];      // running sum of TW over quarters < q'
        float B = tws_s[0][ray];     // running sum of TWS
        float tot = ai_s[0][ray];
        #pragma unroll
        for (int qq2 = 1; qq2 < 4; qq2++) {
            const float tw  = tw_s [qq2][ray];
            const float tws = tws_s[qq2][ray];
            tot += ai_s[qq2][ray];
            tot = fmaf(A, tws, tot);
            tot = fmaf(-B, tw, tot);
            A += tw;
            B += tws;
        }
        out[R0 + ray] = tot * __fdividef(1.0f, fr - nr);
    }
}

extern "C" void kernel_launch(void* const* d_in, const int* in_sizes, int n_in,
                              void* d_out, int out_size)
{
    const float* w   = (const float*)d_in[0]; // weights [R,128,1]
    const float* z   = (const float*)d_in[1]; // z_vals  [R,129]
    const float* nr  = (const float*)d_in[2]; // near    [R,1]
    const float* fr  = (const float*)d_in[3]; // far     [R,1]
    float*       out = (float*)d_out;         // [R,1]

    const int R = in_sizes[0] / 128;          // 8192
    distortion_loss_kernel<<<R / RAYS_PER_CTA, THREADS>>>(w, z, nr, fr, out);
}